// round 15
// baseline (speedup 1.0000x reference)
#include <cuda_runtime.h>
#include <math.h>
#include <stdint.h>

#define B  8
#define C  64
#define Hc 256
#define Wc 256
#define CR 128
#define HR 128
#define WR 128

__device__ float g_scores[B * CR];
__device__ int   g_idx[B * C];
__device__ int   g_done[B];      // zero-init; reset by the topk CTA each call

// ---------------------------------------------------------------------------
// Kernel 1: analytic upsample-mean score + inline topk (proven R12 version).
// ---------------------------------------------------------------------------
__global__ void __launch_bounds__(256) scores_kernel(const float* __restrict__ readout) {
    __shared__ float wA[HR];
    __shared__ float red[8];
    __shared__ float tsv[CR];
    __shared__ int   tsi[CR];
    __shared__ int   s_last;

    const int tid = threadIdx.x;
    const int plane = blockIdx.x;          // b*CR + cr
    const int b = plane >> 7;

    if (tid < HR) wA[tid] = 0.0f;
    __syncthreads();
    {
        const float cst = (float)(127.0 / 255.0);
        float pos = (float)tid * cst;
        int i0 = (int)pos;
        if (i0 > HR - 2) i0 = HR - 2;
        float w = pos - (float)i0;
        atomicAdd(&wA[i0], 1.0f - w);
        atomicAdd(&wA[i0 + 1], w);
    }
    __syncthreads();

    const float4* __restrict__ src =
        (const float4*)(readout + (size_t)plane * (HR * WR));

    float acc0 = 0.f, acc1 = 0.f, acc2 = 0.f, acc3 = 0.f;
    #pragma unroll
    for (int half = 0; half < 2; half++) {
        float4 v[8];
        #pragma unroll
        for (int j = 0; j < 8; j++)
            v[j] = src[tid + (half * 8 + j) * 256];
        #pragma unroll
        for (int j = 0; j < 8; j++) {
            int base = (tid + (half * 8 + j) * 256) << 2;
            int row = base >> 7;
            int col = base & 127;
            float wr = wA[row];
            float s = wA[col] * v[j].x + wA[col + 1] * v[j].y +
                      wA[col + 2] * v[j].z + wA[col + 3] * v[j].w;
            if (j == 0 || j == 4) acc0 += wr * s;
            else if (j == 1 || j == 5) acc1 += wr * s;
            else if (j == 2 || j == 6) acc2 += wr * s;
            else acc3 += wr * s;
        }
    }

    float acc = (acc0 + acc1) + (acc2 + acc3);
    #pragma unroll
    for (int s = 16; s > 0; s >>= 1)
        acc += __shfl_down_sync(0xffffffffu, acc, s);
    if ((tid & 31) == 0) red[tid >> 5] = acc;
    __syncthreads();

    if (tid == 0) {
        float t = 0.f;
        #pragma unroll
        for (int w2 = 0; w2 < 8; w2++) t += red[w2];
        g_scores[plane] = t * (1.0f / (float)(Hc * Wc));
        __threadfence();
        int old = atomicAdd(&g_done[b], 1);
        s_last = (old == CR - 1) ? 1 : 0;
    }
    __syncthreads();

    if (!s_last) return;

    __threadfence();
    if (tid < CR) {
        tsv[tid] = __ldcg(&g_scores[b * CR + tid]);
        tsi[tid] = tid;
    }
    __syncthreads();

    for (int k = 2; k <= CR; k <<= 1) {
        for (int j = k >> 1; j > 0; j >>= 1) {
            if (tid < CR) {
                int ixj = tid ^ j;
                if (ixj > tid) {
                    float va = tsv[tid], vb = tsv[ixj];
                    int   ia = tsi[tid], ib = tsi[ixj];
                    bool first = (va > vb) || (va == vb && ia < ib);
                    bool ascSeg = ((tid & k) == 0);
                    bool doSwap = ascSeg ? (!first) : first;
                    if (doSwap) {
                        tsv[tid] = vb; tsv[ixj] = va;
                        tsi[tid] = ib; tsi[ixj] = ia;
                    }
                }
            }
            __syncthreads();
        }
    }

    if (tid < C) g_idx[b * C + tid] = tsi[tid];
    if (tid == 0) g_done[b] = 0;
}

// ---------------------------------------------------------------------------
// Kernel 2: fused 2x-upsample + gated blend. Static stencil + row-pair reuse,
// register-lean variant for 6 CTAs/SM: only 2 x-rows in flight pre-barrier,
// vertical lerps computed per row pair.
// ---------------------------------------------------------------------------
__global__ void __launch_bounds__(256, 6) fuse_kernel(
    const float* __restrict__ x,
    const float* __restrict__ readout,
    const float* __restrict__ weight,
    const float* __restrict__ bias,
    float* __restrict__ out)
{
    __shared__ float srow2[10 * 128];   // [row][0..63]=even cols, [64..127]=odd

    const int plane = blockIdx.z;
    const int b = plane >> 6;
    const int c = plane & (C - 1);
    const int ch = g_idx[plane];

    const float* __restrict__ rsrc =
        readout + ((size_t)b * CR + ch) * (HR * WR);

    const int y0 = blockIdx.y << 4;           // 16 output rows per block
    const int n0 = y0 >> 1;
    const int iy_lo = (n0 - 1 > 0) ? n0 - 1 : 0;
    const int iy_hi = (n0 + 8 < HR - 1) ? n0 + 8 : HR - 1;
    const int nrows = iy_hi - iy_lo + 1;      // 9..10

    const int tid = threadIdx.x;

    // ---- front-batched stage loads (nrows*32 slots over 256 threads) ----
    const int nslots = nrows * 32;
    float4 sv0, sv1;
    const bool st0 = (tid < nslots);
    const bool st1 = (tid + 256 < nslots);
    if (st0)
        sv0 = __ldg((const float4*)(rsrc + (iy_lo + (tid >> 5)) * WR + ((tid & 31) << 2)));
    if (st1)
        sv1 = __ldg((const float4*)(rsrc + (iy_lo + ((tid + 256) >> 5)) * WR + (((tid + 256) & 31) << 2)));

    const int tx = tid & 63;
    const int ty = tid >> 6;
    const int x0 = tx << 2;
    const int yb = y0 + (ty << 2);            // this thread's first output row
    const size_t o0 = ((size_t)plane * Hc + yb) * Wc + x0;

    // only first 2 x-rows in flight across the barrier
    float4 xv0 = __ldcs((const float4*)(x + o0));
    float4 xv1 = __ldcs((const float4*)(x + o0 + Wc));

    // deswizzled stage writes: even cols -> [0..63], odd cols -> [64..127]
    if (st0) {
        float* base = srow2 + (tid >> 5) * 128;
        int q = tid & 31;
        ((float2*)base)[q]        = make_float2(sv0.x, sv0.z);
        ((float2*)(base + 64))[q] = make_float2(sv0.y, sv0.w);
    }
    if (st1) {
        float* base = srow2 + ((tid + 256) >> 5) * 128;
        int q = (tid + 256) & 31;
        ((float2*)base)[q]        = make_float2(sv1.x, sv1.z);
        ((float2*)(base + 64))[q] = make_float2(sv1.y, sv1.w);
    }
    __syncthreads();

    const float w0c = __ldg(weight + 2 * c);
    const float w1c = __ldg(weight + 2 * c + 1);
    const float bsc = __ldg(bias + c);

    // ---- static horizontal constants (per thread) ----
    const float inv255 = 1.0f / 255.0f;
    const float m0 = (float)(2 * tx);
    const float w0h = 1.0f - m0 * inv255;
    const float w1h = (127.0f - m0) * inv255;
    const float w2h = 1.0f - (m0 + 1.0f) * inv255;
    const float w3h = (126.0f - m0) * inv255;
    const int txm = (tx > 0) ? tx - 1 : 0;
    const int txp = (tx < 63) ? tx + 1 : 63;
    const int cof0 = 64 + txm, cof1 = tx, cof2 = 64 + tx, cof3 = txp;

    // ---- vertical: rows yb..yb+3 need src rows n-1, n, n+1, n+2 ----
    const int n = yb >> 1;
    const float fn = (float)n;
    const float w_e0 = 1.0f - fn * inv255;
    const float w_o0 = (127.0f - fn) * inv255;
    const float w_e1 = 1.0f - (fn + 1.0f) * inv255;
    const float w_o1 = (126.0f - fn) * inv255;

    int rA = n - 1; if (rA < 0) rA = 0;
    int rD = n + 2; if (rD > HR - 1) rD = HR - 1;
    const float* __restrict__ pA = srow2 + (rA    - iy_lo) * 128;
    const float* __restrict__ pB = srow2 + (n     - iy_lo) * 128;
    const float* __restrict__ pC = srow2 + (n + 1 - iy_lo) * 128;
    const float* __restrict__ pD = srow2 + (rD    - iy_lo) * 128;

    float aB0 = pB[cof0], aB1 = pB[cof1], aB2 = pB[cof2], aB3 = pB[cof3];
    float aC0 = pC[cof0], aC1 = pC[cof1], aC2 = pC[cof2], aC3 = pC[cof3];

    // ---------- rows 0,1 (uses pA and pB/pC) ----------
    {
        float aA0 = pA[cof0], aA1 = pA[cof1], aA2 = pA[cof2], aA3 = pA[cof3];

        float v00 = fmaf(w_e0, aB0 - aA0, aA0);
        float v01 = fmaf(w_e0, aB1 - aA1, aA1);
        float v02 = fmaf(w_e0, aB2 - aA2, aA2);
        float v03 = fmaf(w_e0, aB3 - aA3, aA3);

        float v10 = fmaf(w_o0, aC0 - aB0, aB0);
        float v11 = fmaf(w_o0, aC1 - aB1, aB1);
        float v12 = fmaf(w_o0, aC2 - aB2, aB2);
        float v13 = fmaf(w_o0, aC3 - aB3, aB3);

        float rv[2][4] = {
            { fmaf(w0h, v01 - v00, v00), fmaf(w1h, v02 - v01, v01),
              fmaf(w2h, v02 - v01, v01), fmaf(w3h, v03 - v02, v02) },
            { fmaf(w0h, v11 - v10, v10), fmaf(w1h, v12 - v11, v11),
              fmaf(w2h, v12 - v11, v11), fmaf(w3h, v13 - v12, v12) } };

        float4 xq[2] = {xv0, xv1};
        #pragma unroll
        for (int r = 0; r < 2; r++) {
            float xs[4] = {xq[r].x, xq[r].y, xq[r].z, xq[r].w};
            float os[4];
            #pragma unroll
            for (int k = 0; k < 4; k++) {
                float t = fmaf(xs[k], w0c, fmaf(rv[r][k], w1c, bsc));
                float gate = __fdividef(1.0f, 1.0f + __expf(-t));
                os[k] = fmaf(gate, rv[r][k] - xs[k], xs[k]);
            }
            __stcs((float4*)(out + o0 + (size_t)r * Wc),
                   make_float4(os[0], os[1], os[2], os[3]));
        }
    }

    // ---------- rows 2,3 (uses pB/pC and pD) ----------
    {
        float4 xv2 = __ldcs((const float4*)(x + o0 + 2 * (size_t)Wc));
        float4 xv3 = __ldcs((const float4*)(x + o0 + 3 * (size_t)Wc));
        float aD0 = pD[cof0], aD1 = pD[cof1], aD2 = pD[cof2], aD3 = pD[cof3];

        float v20 = fmaf(w_e1, aC0 - aB0, aB0);
        float v21 = fmaf(w_e1, aC1 - aB1, aB1);
        float v22 = fmaf(w_e1, aC2 - aB2, aB2);
        float v23 = fmaf(w_e1, aC3 - aB3, aB3);

        float v30 = fmaf(w_o1, aD0 - aC0, aC0);
        float v31 = fmaf(w_o1, aD1 - aC1, aC1);
        float v32 = fmaf(w_o1, aD2 - aC2, aC2);
        float v33 = fmaf(w_o1, aD3 - aC3, aC3);

        float rv[2][4] = {
            { fmaf(w0h, v21 - v20, v20), fmaf(w1h, v22 - v21, v21),
              fmaf(w2h, v22 - v21, v21), fmaf(w3h, v23 - v22, v22) },
            { fmaf(w0h, v31 - v30, v30), fmaf(w1h, v32 - v31, v31),
              fmaf(w2h, v32 - v31, v31), fmaf(w3h, v33 - v32, v32) } };

        float4 xq[2] = {xv2, xv3};
        #pragma unroll
        for (int r = 0; r < 2; r++) {
            float xs[4] = {xq[r].x, xq[r].y, xq[r].z, xq[r].w};
            float os[4];
            #pragma unroll
            for (int k = 0; k < 4; k++) {
                float t = fmaf(xs[k], w0c, fmaf(rv[r][k], w1c, bsc));
                float gate = __fdividef(1.0f, 1.0f + __expf(-t));
                os[k] = fmaf(gate, rv[r][k] - xs[k], xs[k]);
            }
            __stcs((float4*)(out + o0 + (size_t)(r + 2) * Wc),
                   make_float4(os[0], os[1], os[2], os[3]));
        }
    }
}

// ---------------------------------------------------------------------------
extern "C" void kernel_launch(void* const* d_in, const int* in_sizes, int n_in,
                              void* d_out, int out_size)
{
    const float* x       = (const float*)d_in[0];
    const float* readout = (const float*)d_in[1];
    const float* weight  = (const float*)d_in[2];
    const float* bias    = (const float*)d_in[3];
    float* out = (float*)d_out;

    scores_kernel<<<B * CR, 256>>>(readout);

    dim3 blk(256, 1, 1);
    dim3 grd(1, Hc / 16, B * C);   // 8192 blocks
    fuse_kernel<<<grd, blk>>>(x, readout, weight, bias, out);
}

// round 16
// speedup vs baseline: 1.0060x; 1.0060x over previous
#include <cuda_runtime.h>
#include <math.h>
#include <stdint.h>

#define B  8
#define C  64
#define Hc 256
#define Wc 256
#define CR 128
#define HR 128
#define WR 128

__device__ float g_scores[B * CR];
__device__ int   g_idx[B * C];
__device__ int   g_done[B];      // zero-init; reset by the topk CTA each call

// ---------------------------------------------------------------------------
// Kernel 1: analytic upsample-mean score + inline topk (proven R12 version)
// + early PDL trigger so the fuse kernel's prologue can overlap our tail.
// ---------------------------------------------------------------------------
__global__ void __launch_bounds__(256) scores_kernel(const float* __restrict__ readout) {
    __shared__ float wA[HR];
    __shared__ float red[8];
    __shared__ float tsv[CR];
    __shared__ int   tsi[CR];
    __shared__ int   s_last;

    const int tid = threadIdx.x;
    const int plane = blockIdx.x;          // b*CR + cr
    const int b = plane >> 7;

    if (tid < HR) wA[tid] = 0.0f;
    __syncthreads();
    {
        const float cst = (float)(127.0 / 255.0);
        float pos = (float)tid * cst;
        int i0 = (int)pos;
        if (i0 > HR - 2) i0 = HR - 2;
        float w = pos - (float)i0;
        atomicAdd(&wA[i0], 1.0f - w);
        atomicAdd(&wA[i0 + 1], w);
    }
    __syncthreads();

    const float4* __restrict__ src =
        (const float4*)(readout + (size_t)plane * (HR * WR));

    float acc0 = 0.f, acc1 = 0.f, acc2 = 0.f, acc3 = 0.f;
    #pragma unroll
    for (int half = 0; half < 2; half++) {
        float4 v[8];
        #pragma unroll
        for (int j = 0; j < 8; j++)
            v[j] = src[tid + (half * 8 + j) * 256];
        #pragma unroll
        for (int j = 0; j < 8; j++) {
            int base = (tid + (half * 8 + j) * 256) << 2;
            int row = base >> 7;
            int col = base & 127;
            float wr = wA[row];
            float s = wA[col] * v[j].x + wA[col + 1] * v[j].y +
                      wA[col + 2] * v[j].z + wA[col + 3] * v[j].w;
            if (j == 0 || j == 4) acc0 += wr * s;
            else if (j == 1 || j == 5) acc1 += wr * s;
            else if (j == 2 || j == 6) acc2 += wr * s;
            else acc3 += wr * s;
        }
    }

    float acc = (acc0 + acc1) + (acc2 + acc3);
    #pragma unroll
    for (int s = 16; s > 0; s >>= 1)
        acc += __shfl_down_sync(0xffffffffu, acc, s);
    if ((tid & 31) == 0) red[tid >> 5] = acc;
    __syncthreads();

    if (tid == 0) {
        float t = 0.f;
        #pragma unroll
        for (int w2 = 0; w2 < 8; w2++) t += red[w2];
        g_scores[plane] = t * (1.0f / (float)(Hc * Wc));
        __threadfence();
        int old = atomicAdd(&g_done[b], 1);
        s_last = (old == CR - 1) ? 1 : 0;
    }
    __syncthreads();

    // allow the dependent fuse kernel's CTAs to launch and run their
    // topk-independent prologue (x loads) while we finish.
    cudaTriggerProgrammaticLaunchCompletion();

    if (!s_last) return;

    __threadfence();
    if (tid < CR) {
        tsv[tid] = __ldcg(&g_scores[b * CR + tid]);
        tsi[tid] = tid;
    }
    __syncthreads();

    for (int k = 2; k <= CR; k <<= 1) {
        for (int j = k >> 1; j > 0; j >>= 1) {
            if (tid < CR) {
                int ixj = tid ^ j;
                if (ixj > tid) {
                    float va = tsv[tid], vb = tsv[ixj];
                    int   ia = tsi[tid], ib = tsi[ixj];
                    bool first = (va > vb) || (va == vb && ia < ib);
                    bool ascSeg = ((tid & k) == 0);
                    bool doSwap = ascSeg ? (!first) : first;
                    if (doSwap) {
                        tsv[tid] = vb; tsv[ixj] = va;
                        tsi[tid] = ib; tsi[ixj] = ia;
                    }
                }
            }
            __syncthreads();
        }
    }

    if (tid < C) g_idx[b * C + tid] = tsi[tid];
    if (tid == 0) g_done[b] = 0;
}

// ---------------------------------------------------------------------------
// Kernel 2: fused 2x-upsample + gated blend (proven R14 body), PDL-split:
// topk-independent prologue (x loads, weights, constants) BEFORE
// cudaGridDependencySynchronize(); g_idx + readout staging after.
// ---------------------------------------------------------------------------
__global__ void __launch_bounds__(256) fuse_kernel(
    const float* __restrict__ x,
    const float* __restrict__ readout,
    const float* __restrict__ weight,
    const float* __restrict__ bias,
    float* __restrict__ out)
{
    __shared__ float srow2[10 * 128];   // [row][0..63]=even cols, [64..127]=odd

    const int plane = blockIdx.z;
    const int b = plane >> 6;
    const int c = plane & (C - 1);

    const int y0 = blockIdx.y << 4;           // 16 output rows per block
    const int n0 = y0 >> 1;
    const int iy_lo = (n0 - 1 > 0) ? n0 - 1 : 0;
    const int iy_hi = (n0 + 8 < HR - 1) ? n0 + 8 : HR - 1;
    const int nrows = iy_hi - iy_lo + 1;      // 9..10

    const int tid = threadIdx.x;
    const int tx = tid & 63;
    const int ty = tid >> 6;
    const int x0 = tx << 2;
    const int yb = y0 + (ty << 2);            // this thread's first output row
    const size_t o0 = ((size_t)plane * Hc + yb) * Wc + x0;

    // ======== PDL prologue: everything independent of g_idx ========
    float4 xv[4];
    #pragma unroll
    for (int r = 0; r < 4; r++)
        xv[r] = __ldcs((const float4*)(x + o0 + (size_t)r * Wc));

    const float w0c = __ldg(weight + 2 * c);
    const float w1c = __ldg(weight + 2 * c + 1);
    const float bsc = __ldg(bias + c);

    const float inv255 = 1.0f / 255.0f;
    const float m0 = (float)(2 * tx);
    const float w0h = 1.0f - m0 * inv255;
    const float w1h = (127.0f - m0) * inv255;
    const float w2h = 1.0f - (m0 + 1.0f) * inv255;
    const float w3h = (126.0f - m0) * inv255;
    const int txm = (tx > 0) ? tx - 1 : 0;
    const int txp = (tx < 63) ? tx + 1 : 63;

    const int n = yb >> 1;
    const float fn = (float)n;
    const float w_e0 = 1.0f - fn * inv255;
    const float w_o0 = (127.0f - fn) * inv255;
    const float w_e1 = 1.0f - (fn + 1.0f) * inv255;
    const float w_o1 = (126.0f - fn) * inv255;

    // ======== wait for scores/topk, then the g_idx-dependent part ========
    cudaGridDependencySynchronize();

    const int ch = g_idx[plane];
    const float* __restrict__ rsrc =
        readout + ((size_t)b * CR + ch) * (HR * WR);

    const int nslots = nrows * 32;
    float4 sv0, sv1;
    const bool st0 = (tid < nslots);
    const bool st1 = (tid + 256 < nslots);
    if (st0)
        sv0 = __ldg((const float4*)(rsrc + (iy_lo + (tid >> 5)) * WR + ((tid & 31) << 2)));
    if (st1)
        sv1 = __ldg((const float4*)(rsrc + (iy_lo + ((tid + 256) >> 5)) * WR + (((tid + 256) & 31) << 2)));

    if (st0) {
        float* base = srow2 + (tid >> 5) * 128;
        int q = tid & 31;
        ((float2*)base)[q]        = make_float2(sv0.x, sv0.z);
        ((float2*)(base + 64))[q] = make_float2(sv0.y, sv0.w);
    }
    if (st1) {
        float* base = srow2 + ((tid + 256) >> 5) * 128;
        int q = (tid + 256) & 31;
        ((float2*)base)[q]        = make_float2(sv1.x, sv1.z);
        ((float2*)(base + 64))[q] = make_float2(sv1.y, sv1.w);
    }
    __syncthreads();

    int rA = n - 1; if (rA < 0) rA = 0;
    int rD = n + 2; if (rD > HR - 1) rD = HR - 1;
    const float* __restrict__ pA = srow2 + (rA    - iy_lo) * 128;
    const float* __restrict__ pB = srow2 + (n     - iy_lo) * 128;
    const float* __restrict__ pC = srow2 + (n + 1 - iy_lo) * 128;
    const float* __restrict__ pD = srow2 + (rD    - iy_lo) * 128;

    float vr[4][4];
    const int cofs[4] = {64 + txm, tx, 64 + tx, txp};   // c0, c1, c2, c3
    #pragma unroll
    for (int q = 0; q < 4; q++) {
        const int cc = cofs[q];
        float a = pA[cc], bv = pB[cc], cv = pC[cc], d = pD[cc];
        vr[0][q] = fmaf(w_e0, bv - a,  a);
        vr[1][q] = fmaf(w_o0, cv - bv, bv);
        vr[2][q] = fmaf(w_e1, cv - bv, bv);
        vr[3][q] = fmaf(w_o1, d  - cv, cv);
    }

    #pragma unroll
    for (int r = 0; r < 4; r++) {
        float c0 = vr[r][0], c1 = vr[r][1], c2 = vr[r][2], c3 = vr[r][3];
        float rv0 = fmaf(w0h, c1 - c0, c0);
        float rv1 = fmaf(w1h, c2 - c1, c1);
        float rv2 = fmaf(w2h, c2 - c1, c1);
        float rv3 = fmaf(w3h, c3 - c2, c2);

        float xs[4] = {xv[r].x, xv[r].y, xv[r].z, xv[r].w};
        float rvv[4] = {rv0, rv1, rv2, rv3};
        float os[4];
        #pragma unroll
        for (int k = 0; k < 4; k++) {
            float t = fmaf(xs[k], w0c, fmaf(rvv[k], w1c, bsc));
            float gate = __fdividef(1.0f, 1.0f + __expf(-t));
            os[k] = fmaf(gate, rvv[k] - xs[k], xs[k]);
        }
        __stcs((float4*)(out + o0 + (size_t)r * Wc),
               make_float4(os[0], os[1], os[2], os[3]));
    }
}

// ---------------------------------------------------------------------------
extern "C" void kernel_launch(void* const* d_in, const int* in_sizes, int n_in,
                              void* d_out, int out_size)
{
    const float* x       = (const float*)d_in[0];
    const float* readout = (const float*)d_in[1];
    const float* weight  = (const float*)d_in[2];
    const float* bias    = (const float*)d_in[3];
    float* out = (float*)d_out;

    scores_kernel<<<B * CR, 256>>>(readout);

    dim3 blk(256, 1, 1);
    dim3 grd(1, Hc / 16, B * C);   // 8192 blocks

    cudaLaunchConfig_t cfg = {};
    cfg.gridDim = grd;
    cfg.blockDim = blk;
    cfg.dynamicSmemBytes = 0;
    cudaLaunchAttribute attr[1];
    attr[0].id = cudaLaunchAttributeProgrammaticStreamSerialization;
    attr[0].val.programmaticStreamSerializationAllowed = 1;
    cfg.attrs = attr;
    cfg.numAttrs = 1;

    cudaError_t err = cudaLaunchKernelEx(&cfg, fuse_kernel,
                                         x, readout, weight, bias, out);
    if (err != cudaSuccess) {
        // fallback: plain launch (gridDepSync is a no-op without PDL)
        cudaGetLastError();
        fuse_kernel<<<grd, blk>>>(x, readout, weight, bias, out);
    }
}

// round 17
// speedup vs baseline: 1.0437x; 1.0374x over previous
#include <cuda_runtime.h>
#include <math.h>
#include <stdint.h>

#define B  8
#define C  64
#define Hc 256
#define Wc 256
#define CR 128
#define HR 128
#define WR 128

__device__ float g_scores[B * CR];
__device__ int   g_idx[B * C];
__device__ int   g_done[B];      // zero-init; reset by the topk CTA each call

// ---------------------------------------------------------------------------
// Kernel 1: analytic upsample-mean score + inline topk (proven R14 version).
// No PDL trigger: CTA exit is the completion signal, so the dependent fuse
// kernel's gridDepSync has full-completion semantics (race-free).
// ---------------------------------------------------------------------------
__global__ void __launch_bounds__(256) scores_kernel(const float* __restrict__ readout) {
    __shared__ float wA[HR];
    __shared__ float red[8];
    __shared__ float tsv[CR];
    __shared__ int   tsi[CR];
    __shared__ int   s_last;

    const int tid = threadIdx.x;
    const int plane = blockIdx.x;          // b*CR + cr
    const int b = plane >> 7;

    if (tid < HR) wA[tid] = 0.0f;
    __syncthreads();
    {
        const float cst = (float)(127.0 / 255.0);
        float pos = (float)tid * cst;
        int i0 = (int)pos;
        if (i0 > HR - 2) i0 = HR - 2;
        float w = pos - (float)i0;
        atomicAdd(&wA[i0], 1.0f - w);
        atomicAdd(&wA[i0 + 1], w);
    }
    __syncthreads();

    const float4* __restrict__ src =
        (const float4*)(readout + (size_t)plane * (HR * WR));

    float acc0 = 0.f, acc1 = 0.f, acc2 = 0.f, acc3 = 0.f;
    #pragma unroll
    for (int half = 0; half < 2; half++) {
        float4 v[8];
        #pragma unroll
        for (int j = 0; j < 8; j++)
            v[j] = src[tid + (half * 8 + j) * 256];
        #pragma unroll
        for (int j = 0; j < 8; j++) {
            int base = (tid + (half * 8 + j) * 256) << 2;
            int row = base >> 7;
            int col = base & 127;
            float wr = wA[row];
            float s = wA[col] * v[j].x + wA[col + 1] * v[j].y +
                      wA[col + 2] * v[j].z + wA[col + 3] * v[j].w;
            if (j == 0 || j == 4) acc0 += wr * s;
            else if (j == 1 || j == 5) acc1 += wr * s;
            else if (j == 2 || j == 6) acc2 += wr * s;
            else acc3 += wr * s;
        }
    }

    float acc = (acc0 + acc1) + (acc2 + acc3);
    #pragma unroll
    for (int s = 16; s > 0; s >>= 1)
        acc += __shfl_down_sync(0xffffffffu, acc, s);
    if ((tid & 31) == 0) red[tid >> 5] = acc;
    __syncthreads();

    if (tid == 0) {
        float t = 0.f;
        #pragma unroll
        for (int w2 = 0; w2 < 8; w2++) t += red[w2];
        g_scores[plane] = t * (1.0f / (float)(Hc * Wc));
        __threadfence();
        int old = atomicAdd(&g_done[b], 1);
        s_last = (old == CR - 1) ? 1 : 0;
    }
    __syncthreads();

    if (!s_last) return;

    __threadfence();
    if (tid < CR) {
        tsv[tid] = __ldcg(&g_scores[b * CR + tid]);
        tsi[tid] = tid;
    }
    __syncthreads();

    for (int k = 2; k <= CR; k <<= 1) {
        for (int j = k >> 1; j > 0; j >>= 1) {
            if (tid < CR) {
                int ixj = tid ^ j;
                if (ixj > tid) {
                    float va = tsv[tid], vb = tsv[ixj];
                    int   ia = tsi[tid], ib = tsi[ixj];
                    bool first = (va > vb) || (va == vb && ia < ib);
                    bool ascSeg = ((tid & k) == 0);
                    bool doSwap = ascSeg ? (!first) : first;
                    if (doSwap) {
                        tsv[tid] = vb; tsv[ixj] = va;
                        tsi[tid] = ib; tsi[ixj] = ia;
                    }
                }
            }
            __syncthreads();
        }
    }

    if (tid < C) g_idx[b * C + tid] = tsi[tid];
    if (tid == 0) g_done[b] = 0;
}

// ---------------------------------------------------------------------------
// Kernel 2: fused 2x-upsample + gated blend (proven R14 body). PDL gap-hiding
// only: gridDepSync is the FIRST statement — no state held across it, no
// overlap contention; CTAs merely pre-launch during scores' tail.
// ---------------------------------------------------------------------------
__global__ void __launch_bounds__(256) fuse_kernel(
    const float* __restrict__ x,
    const float* __restrict__ readout,
    const float* __restrict__ weight,
    const float* __restrict__ bias,
    float* __restrict__ out)
{
    cudaGridDependencySynchronize();

    __shared__ float srow2[10 * 128];   // [row][0..63]=even cols, [64..127]=odd

    const int plane = blockIdx.z;
    const int b = plane >> 6;
    const int c = plane & (C - 1);
    const int ch = g_idx[plane];

    const float* __restrict__ rsrc =
        readout + ((size_t)b * CR + ch) * (HR * WR);

    const int y0 = blockIdx.y << 4;           // 16 output rows per block
    const int n0 = y0 >> 1;
    const int iy_lo = (n0 - 1 > 0) ? n0 - 1 : 0;
    const int iy_hi = (n0 + 8 < HR - 1) ? n0 + 8 : HR - 1;
    const int nrows = iy_hi - iy_lo + 1;      // 9..10

    const int tid = threadIdx.x;

    // ---- front-batched stage loads (nrows*32 slots over 256 threads) ----
    const int nslots = nrows * 32;
    float4 sv0, sv1;
    const bool st0 = (tid < nslots);
    const bool st1 = (tid + 256 < nslots);
    if (st0)
        sv0 = __ldg((const float4*)(rsrc + (iy_lo + (tid >> 5)) * WR + ((tid & 31) << 2)));
    if (st1)
        sv1 = __ldg((const float4*)(rsrc + (iy_lo + ((tid + 256) >> 5)) * WR + (((tid + 256) & 31) << 2)));

    // ---- front-batched x loads: 4 CONSECUTIVE rows, dense float4 lanes ----
    const int tx = tid & 63;
    const int ty = tid >> 6;
    const int x0 = tx << 2;
    const int yb = y0 + (ty << 2);            // this thread's first output row

    size_t o0 = ((size_t)plane * Hc + yb) * Wc + x0;
    float4 xv[4];
    #pragma unroll
    for (int r = 0; r < 4; r++)
        xv[r] = __ldcs((const float4*)(x + o0 + (size_t)r * Wc));

    // deswizzled stage writes: even cols -> [0..63], odd cols -> [64..127]
    if (st0) {
        float* base = srow2 + (tid >> 5) * 128;
        int q = tid & 31;
        ((float2*)base)[q]        = make_float2(sv0.x, sv0.z);
        ((float2*)(base + 64))[q] = make_float2(sv0.y, sv0.w);
    }
    if (st1) {
        float* base = srow2 + ((tid + 256) >> 5) * 128;
        int q = (tid + 256) & 31;
        ((float2*)base)[q]        = make_float2(sv1.x, sv1.z);
        ((float2*)(base + 64))[q] = make_float2(sv1.y, sv1.w);
    }
    __syncthreads();

    const float w0c = __ldg(weight + 2 * c);
    const float w1c = __ldg(weight + 2 * c + 1);
    const float bsc = __ldg(bias + c);

    // ---- static horizontal constants (per thread) ----
    const float inv255 = 1.0f / 255.0f;
    const float m0 = (float)(2 * tx);
    const float w0h = 1.0f - m0 * inv255;
    const float w1h = (127.0f - m0) * inv255;
    const float w2h = 1.0f - (m0 + 1.0f) * inv255;
    const float w3h = (126.0f - m0) * inv255;
    const int txm = (tx > 0) ? tx - 1 : 0;
    const int txp = (tx < 63) ? tx + 1 : 63;

    // ---- vertical: rows yb..yb+3 need src rows n-1, n, n+1, n+2 ----
    const int n = yb >> 1;
    const float fn = (float)n;
    const float w_e0 = 1.0f - fn * inv255;
    const float w_o0 = (127.0f - fn) * inv255;
    const float w_e1 = 1.0f - (fn + 1.0f) * inv255;
    const float w_o1 = (126.0f - fn) * inv255;

    int rA = n - 1; if (rA < 0) rA = 0;
    int rD = n + 2; if (rD > HR - 1) rD = HR - 1;
    const float* __restrict__ pA = srow2 + (rA    - iy_lo) * 128;
    const float* __restrict__ pB = srow2 + (n     - iy_lo) * 128;
    const float* __restrict__ pC = srow2 + (n + 1 - iy_lo) * 128;
    const float* __restrict__ pD = srow2 + (rD    - iy_lo) * 128;

    float vr[4][4];
    const int cofs[4] = {64 + txm, tx, 64 + tx, txp};   // c0, c1, c2, c3
    #pragma unroll
    for (int q = 0; q < 4; q++) {
        const int cc = cofs[q];
        float a = pA[cc], bv = pB[cc], cv = pC[cc], d = pD[cc];
        vr[0][q] = fmaf(w_e0, bv - a,  a);
        vr[1][q] = fmaf(w_o0, cv - bv, bv);
        vr[2][q] = fmaf(w_e1, cv - bv, bv);
        vr[3][q] = fmaf(w_o1, d  - cv, cv);
    }

    #pragma unroll
    for (int r = 0; r < 4; r++) {
        float c0 = vr[r][0], c1 = vr[r][1], c2 = vr[r][2], c3 = vr[r][3];
        float rv0 = fmaf(w0h, c1 - c0, c0);
        float rv1 = fmaf(w1h, c2 - c1, c1);
        float rv2 = fmaf(w2h, c2 - c1, c1);
        float rv3 = fmaf(w3h, c3 - c2, c2);

        float xs[4] = {xv[r].x, xv[r].y, xv[r].z, xv[r].w};
        float rvv[4] = {rv0, rv1, rv2, rv3};
        float os[4];
        #pragma unroll
        for (int k = 0; k < 4; k++) {
            float t = fmaf(xs[k], w0c, fmaf(rvv[k], w1c, bsc));
            float gate = __fdividef(1.0f, 1.0f + __expf(-t));
            os[k] = fmaf(gate, rvv[k] - xs[k], xs[k]);
        }
        __stcs((float4*)(out + o0 + (size_t)r * Wc),
               make_float4(os[0], os[1], os[2], os[3]));
    }
}

// ---------------------------------------------------------------------------
extern "C" void kernel_launch(void* const* d_in, const int* in_sizes, int n_in,
                              void* d_out, int out_size)
{
    const float* x       = (const float*)d_in[0];
    const float* readout = (const float*)d_in[1];
    const float* weight  = (const float*)d_in[2];
    const float* bias    = (const float*)d_in[3];
    float* out = (float*)d_out;

    scores_kernel<<<B * CR, 256>>>(readout);

    dim3 blk(256, 1, 1);
    dim3 grd(1, Hc / 16, B * C);   // 8192 blocks

    cudaLaunchConfig_t cfg = {};
    cfg.gridDim = grd;
    cfg.blockDim = blk;
    cfg.dynamicSmemBytes = 0;
    cudaLaunchAttribute attr[1];
    attr[0].id = cudaLaunchAttributeProgrammaticStreamSerialization;
    attr[0].val.programmaticStreamSerializationAllowed = 1;
    cfg.attrs = attr;
    cfg.numAttrs = 1;

    cudaError_t err = cudaLaunchKernelEx(&cfg, fuse_kernel,
                                         x, readout, weight, bias, out);
    if (err != cudaSuccess) {
        // fallback: plain launch (gridDepSync is a no-op without PDL)
        cudaGetLastError();
        fuse_kernel<<<grd, blk>>>(x, readout, weight, bias, out);
    }
}